// round 8
// baseline (speedup 1.0000x reference)
#include <cuda_runtime.h>
#include <cuda_fp16.h>
#include <cstdint>

// Problem dims
#define K_DIM 8192
#define N_DIM 8192

// GEMM tiling
#define KSPLIT 8
#define KCHUNK (K_DIM / KSPLIT)          // 1024
#define NKSTEPS (KCHUNK / 16)            // 64 k-steps of 16
#define CTA_N 256
#define NSTRIPS (N_DIM / CTA_N)          // 32
#define WARPS 8
#define WARP_N 32                        // 4 n-tiles of 8 per warp
#define STAGES 4

// Shared-memory stage layout
#define W_ROW_BYTES (CTA_N * 4)                  // 1024
#define W_ROW_STRIDE (W_ROW_BYTES + 16)          // 1040 (pad -> conflict-free frag LDS)
#define W_STAGE_BYTES (16 * W_ROW_STRIDE)        // 16640
#define A_STAGE_BYTES 1024                       // 2 t-tiles * 32 lanes * 16B
#define STAGE_BYTES (W_STAGE_BYTES + A_STAGE_BYTES)  // 17664
#define SMEM_BYTES (STAGES * STAGE_BYTES)        // 70656 (dynamic smem)

// Scratch (allocation-free: __device__ globals)
__device__ __align__(16) __half g_Apack[32 * K_DIM];    // 512 KB, fragment-packed A
__device__ __align__(16) float g_Yp[KSPLIT][32 * N_DIM]; // 8 MB partials
__device__ float g_corr[32];                             // 1152 * rowsum(fp16(x*s))

// ---------------------------------------------------------------------------
// Kernel 1: blocks [0,512): fold scaler into x, fp16, fragment-pack A.
//           blocks [512,544): per-batch-row bias-correction sums.
// ---------------------------------------------------------------------------
__global__ void prep_pack_kernel(const float* __restrict__ x,
                                 const float* __restrict__ scaler) {
    float s = scaler[0];
    if (blockIdx.x < 512) {
        int idx = blockIdx.x * blockDim.x + threadIdx.x;   // 0 .. 32*4096-1
        int r  = idx >> 12;          // A row 0..31
        int kp = idx & 4095;         // k pair index
        int k  = kp * 2;
        float2 xv = *reinterpret_cast<const float2*>(&x[r * K_DIM + k]);
        __half2 h2 = __floats2half2_rn(xv.x * s, xv.y * s);  // low = even k
        unsigned packed = *reinterpret_cast<unsigned*>(&h2);
        // Fragment slot order {a0,a1,a2,a3} = {(g,klo),(g+8,klo),(g,khi),(g+8,khi)}
        int ks = k >> 4;
        int kk = k & 15;
        int t  = r >> 4;             // 0..1
        int gg = r & 15;
        int gq = gg & 7;
        int tg = (kk >> 1) & 3;
        int slot = ((kk >> 3) << 1) | (gg >> 3);
        size_t off = (size_t)ks * A_STAGE_BYTES + t * 512 + (gq * 4 + tg) * 16 + slot * 4;
        *(unsigned*)((char*)g_Apack + off) = packed;
    } else {
        // Correction: g_corr[row] = 1152 * sum_k fp16(x[row][k] * s)
        int row = blockIdx.x - 512;  // 0..31
        __shared__ float red[256];
        float acc = 0.0f;
        const float4* xr = reinterpret_cast<const float4*>(&x[row * K_DIM]);
        #pragma unroll
        for (int it = 0; it < K_DIM / (256 * 4); it++) {
            float4 v = xr[it * 256 + threadIdx.x];
            acc += __half2float(__float2half_rn(v.x * s));
            acc += __half2float(__float2half_rn(v.y * s));
            acc += __half2float(__float2half_rn(v.z * s));
            acc += __half2float(__float2half_rn(v.w * s));
        }
        red[threadIdx.x] = acc;
        __syncthreads();
        for (int off = 128; off > 0; off >>= 1) {
            if (threadIdx.x < off) red[threadIdx.x] += red[threadIdx.x + off];
            __syncthreads();
        }
        if (threadIdx.x == 0) g_corr[row] = 1152.0f * red[0];
    }
}

// ---------------------------------------------------------------------------
// Kernel 2: cp.async-pipelined fused dequant GEMM (mma m16n8k16 f16.f32).
// CTA: 256 n-cols, 8 warps (warp_n = 32, m = 32). 4-stage dynamic-smem pipeline.
// B conversion via integer bias trick: fp16bits(1152+w) = w + 0x6480 (low 16).
// ---------------------------------------------------------------------------
__global__ __launch_bounds__(256, 2) void gemm_kernel(const int* __restrict__ W) {
    extern __shared__ __align__(16) char sm[];

    const int tid  = threadIdx.x;
    const int lane = tid & 31;
    const int warp = tid >> 5;
    const int g    = lane >> 2;
    const int tg   = lane & 3;

    const int n0cta = blockIdx.x * CTA_N;
    const int krow0 = blockIdx.y * KCHUNK;     // first k row of this split
    const int ks0   = blockIdx.y * NKSTEPS;    // first global kstep (for A pack)

    // cp.async coords: W stage = 16 rows x 1024B = 1024 granules of 16B.
    // Each thread copies 4 W granules: rows (tid>>6)+4j, col granule tid&63.
    const int wr = tid >> 6;                   // 0..3
    const int wc = tid & 63;                   // 16B granule in row
    const char* wsrc0 = (const char*)(W + (size_t)(krow0 + wr) * N_DIM + n0cta) + wc * 16;
    const char* asrc0 = (const char*)g_Apack + (size_t)ks0 * A_STAGE_BYTES + tid * 16;
    const unsigned sm_base = (unsigned)__cvta_generic_to_shared(sm);

    auto issue_stage = [&](int p) {
        if (p < NKSTEPS) {
            unsigned d  = sm_base + (p & (STAGES - 1)) * STAGE_BYTES;
            const char* ws = wsrc0 + (size_t)p * 16 * N_DIM * 4;
            unsigned d0 = d + wr * W_ROW_STRIDE + wc * 16;
            #pragma unroll
            for (int j = 0; j < 4; j++) {
                asm volatile("cp.async.cg.shared.global [%0], [%1], 16;\n"
                             :: "r"(d0 + j * 4 * W_ROW_STRIDE),
                                "l"(ws + (size_t)j * 4 * N_DIM * 4));
            }
            if (tid < 64) {
                asm volatile("cp.async.ca.shared.global [%0], [%1], 16;\n"
                             :: "r"(d + W_STAGE_BYTES + tid * 16),
                                "l"(asrc0 + (size_t)p * A_STAGE_BYTES));
            }
        }
        asm volatile("cp.async.commit_group;\n" ::);
    };

    issue_stage(0);
    issue_stage(1);
    issue_stage(2);

    float acc[2][4][4] = {};

    for (int ks = 0; ks < NKSTEPS; ks++) {
        asm volatile("cp.async.wait_group 2;\n" ::);
        __syncthreads();
        issue_stage(ks + 3);   // refills the buffer consumed at iteration ks-1

        const unsigned sb = sm_base + (ks & (STAGES - 1)) * STAGE_BYTES;

        // A fragments: 2 x LDS.128 (broadcast across warps)
        unsigned a[2][4];
        const unsigned ab = sb + W_STAGE_BYTES + lane * 16;
        #pragma unroll
        for (int t = 0; t < 2; t++) {
            asm volatile("ld.shared.v4.b32 {%0,%1,%2,%3}, [%4];"
                         : "=r"(a[t][0]), "=r"(a[t][1]), "=r"(a[t][2]), "=r"(a[t][3])
                         : "r"(ab + t * 512));
        }

        #pragma unroll
        for (int i = 0; i < 4; i++) {
            // B ints from smem: rows tg*2 + {0,1,8,9}, col warp*32 + i*8 + g.
            // stride 1040B -> bank = (8*tg + g + 8*i + 8*warp)%32 : conflict-free per i.
            const unsigned wb = sb + (tg * 2) * W_ROW_STRIDE + (warp * WARP_N + i * 8 + g) * 4;
            int w0, w1, w2, w3;
            asm volatile("ld.shared.b32 %0, [%1];" : "=r"(w0) : "r"(wb));
            asm volatile("ld.shared.b32 %0, [%1];" : "=r"(w1) : "r"(wb + W_ROW_STRIDE));
            asm volatile("ld.shared.b32 %0, [%1];" : "=r"(w2) : "r"(wb + 8 * W_ROW_STRIDE));
            asm volatile("ld.shared.b32 %0, [%1];" : "=r"(w3) : "r"(wb + 9 * W_ROW_STRIDE));
            // fp16 bits of (1152 + w) = w + 0x6480 (low 16 bits); pack pairs.
            unsigned b0 = __byte_perm((unsigned)(w0 + 0x6480), (unsigned)(w1 + 0x6480), 0x5410);
            unsigned b1 = __byte_perm((unsigned)(w2 + 0x6480), (unsigned)(w3 + 0x6480), 0x5410);

            #pragma unroll
            for (int t = 0; t < 2; t++) {
                float* c = acc[t][i];
                asm volatile(
                    "mma.sync.aligned.m16n8k16.row.col.f32.f16.f16.f32 "
                    "{%0,%1,%2,%3}, {%4,%5,%6,%7}, {%8,%9}, {%0,%1,%2,%3};"
                    : "+f"(c[0]), "+f"(c[1]), "+f"(c[2]), "+f"(c[3])
                    : "r"(a[t][0]), "r"(a[t][1]), "r"(a[t][2]), "r"(a[t][3]),
                      "r"(b0), "r"(b1));
            }
        }
    }

    // Epilogue: fp32 partials (bias still included; removed in reduce)
    float* yp = g_Yp[blockIdx.y];
    #pragma unroll
    for (int t = 0; t < 2; t++) {
        #pragma unroll
        for (int i = 0; i < 4; i++) {
            const int row = t * 16 + g;
            const int col = n0cta + warp * WARP_N + i * 8 + tg * 2;
            *reinterpret_cast<float2*>(&yp[(size_t)row * N_DIM + col]) =
                make_float2(acc[t][i][0], acc[t][i][1]);
            *reinterpret_cast<float2*>(&yp[(size_t)(row + 8) * N_DIM + col]) =
                make_float2(acc[t][i][2], acc[t][i][3]);
        }
    }
}

// ---------------------------------------------------------------------------
// Kernel 3: reduce k-splits (float4), subtract bias correction.
// ---------------------------------------------------------------------------
__global__ void reduce_kernel(float* __restrict__ out) {
    int idx4 = blockIdx.x * blockDim.x + threadIdx.x;   // 0 .. 32*2048-1
    int b = idx4 >> 11;
    float c = g_corr[b];
    float4 s = make_float4(-c, -c, -c, -c);
    #pragma unroll
    for (int sp = 0; sp < KSPLIT; sp++) {
        float4 v = reinterpret_cast<const float4*>(g_Yp[sp])[idx4];
        s.x += v.x; s.y += v.y; s.z += v.z; s.w += v.w;
    }
    reinterpret_cast<float4*>(out)[idx4] = s;
}

// ---------------------------------------------------------------------------
extern "C" void kernel_launch(void* const* d_in, const int* in_sizes, int n_in,
                              void* d_out, int out_size) {
    const float* x      = (const float*)d_in[0];   // [32, 8192] fp32
    const int*   w      = (const int*)d_in[1];     // [8192, 8192] int32 (int8-valued)
    const float* scaler = (const float*)d_in[2];   // [1] fp32
    float* out = (float*)d_out;                    // [32, 8192] fp32

    static bool attr_set = false;
    if (!attr_set) {
        cudaFuncSetAttribute(gemm_kernel,
                             cudaFuncAttributeMaxDynamicSharedMemorySize, SMEM_BYTES);
        attr_set = true;
    }

    prep_pack_kernel<<<544, 256>>>(x, scaler);
    gemm_kernel<<<dim3(NSTRIPS, KSPLIT), 256, SMEM_BYTES>>>(w);
    reduce_kernel<<<128, 512>>>(out);
}

// round 9
// speedup vs baseline: 1.3594x; 1.3594x over previous
#include <cuda_runtime.h>
#include <cuda_fp16.h>
#include <cstdint>

// Problem dims
#define K_DIM 8192
#define N_DIM 8192

// GEMM tiling (reverted to the empirically-best R5 shape)
#define KSPLIT 4
#define KCHUNK (K_DIM / KSPLIT)          // 2048
#define NKSTEPS (KCHUNK / 16)            // 128 k-steps of 16
#define CTA_N 128
#define NSTRIPS (N_DIM / CTA_N)          // 64
#define WARPS 8
#define WARP_N 16                        // 2 n-tiles of 8 per warp
#define STAGES 5                         // deeper pipeline (was 4)

// Shared-memory stage layout
#define W_ROW_BYTES (CTA_N * 4)                  // 512
#define W_ROW_STRIDE (W_ROW_BYTES + 16)          // 528 (pad -> conflict-free frag LDS)
#define W_STAGE_BYTES (16 * W_ROW_STRIDE)        // 8448
#define A_STAGE_BYTES 1024                       // 2 t-tiles * 32 lanes * 16B
#define STAGE_BYTES (W_STAGE_BYTES + A_STAGE_BYTES)  // 9472
#define SMEM_BYTES (STAGES * STAGE_BYTES)        // 47360 (< 48KB static limit)

// Scratch (allocation-free: __device__ globals)
__device__ __align__(16) __half g_Apack[32 * K_DIM];     // 512 KB, fragment-packed A
__device__ __align__(16) float g_Yp[KSPLIT][32 * N_DIM]; // 4 MB partials

// ---------------------------------------------------------------------------
// Kernel 1: fold scaler into x, fp16, fragment-pack A.
// Inverted mapping: one thread produces one 16B fragment line (4 slots),
// so all g_Apack stores are fully-coalesced STG.128.
// Line L (16B): ks = L>>6, t = (L>>5)&1, lane = L&31 (g = lane>>2, tg = lane&3)
// slots = { (r0,k0), (r0+8,k0), (r0,k0+8), (r0+8,k0+8) },
//   r0 = t*16+g, k0 = ks*16+tg*2, each slot = half2 of k, k+1 (low = even k).
// ---------------------------------------------------------------------------
__global__ void prep_pack_kernel(const float* __restrict__ x,
                                 const float* __restrict__ scaler) {
    int L = blockIdx.x * blockDim.x + threadIdx.x;   // 0 .. 32767
    float s = scaler[0];
    int ks   = L >> 6;
    int rem  = L & 63;
    int t    = rem >> 5;
    int lane = rem & 31;
    int g  = lane >> 2;
    int tg = lane & 3;
    int r0 = t * 16 + g;
    int k0 = ks * 16 + tg * 2;

    float2 v00 = *reinterpret_cast<const float2*>(&x[(size_t)r0 * K_DIM + k0]);
    float2 v10 = *reinterpret_cast<const float2*>(&x[(size_t)(r0 + 8) * K_DIM + k0]);
    float2 v01 = *reinterpret_cast<const float2*>(&x[(size_t)r0 * K_DIM + k0 + 8]);
    float2 v11 = *reinterpret_cast<const float2*>(&x[(size_t)(r0 + 8) * K_DIM + k0 + 8]);

    __half2 h00 = __floats2half2_rn(v00.x * s, v00.y * s);
    __half2 h10 = __floats2half2_rn(v10.x * s, v10.y * s);
    __half2 h01 = __floats2half2_rn(v01.x * s, v01.y * s);
    __half2 h11 = __floats2half2_rn(v11.x * s, v11.y * s);

    uint4 o;
    o.x = *reinterpret_cast<unsigned*>(&h00);
    o.y = *reinterpret_cast<unsigned*>(&h10);
    o.z = *reinterpret_cast<unsigned*>(&h01);
    o.w = *reinterpret_cast<unsigned*>(&h11);
    reinterpret_cast<uint4*>(g_Apack)[L] = o;
}

// ---------------------------------------------------------------------------
// Kernel 2: cp.async-pipelined fused dequant GEMM (mma m16n8k16 f16.f32).
// CTA: 128 n-cols, 8 warps (warp_n = 16, m = 32). 5-stage smem pipeline.
// ---------------------------------------------------------------------------
__global__ __launch_bounds__(256, 2) void gemm_kernel(const int* __restrict__ W) {
    __shared__ __align__(16) char sm[SMEM_BYTES];

    const int tid  = threadIdx.x;
    const int lane = tid & 31;
    const int warp = tid >> 5;
    const int g    = lane >> 2;
    const int tg   = lane & 3;

    const int n0cta = blockIdx.x * CTA_N;
    const int krow0 = blockIdx.y * KCHUNK;     // first k row of this split
    const int ks0   = blockIdx.y * NKSTEPS;    // first global kstep (for A pack)

    // cp.async thread coords: each thread copies two 16B W granules;
    // threads [0,64) also copy one 16B A granule.
    const int r0  = tid >> 5;                  // W tile row 0..7 (and +8)
    const int c16 = tid & 31;                  // 16B column granule within row
    const char* wsrc0 = (const char*)(W + (size_t)(krow0 + r0) * N_DIM + n0cta + c16 * 4);
    const char* asrc0 = (const char*)g_Apack + (size_t)ks0 * A_STAGE_BYTES + tid * 16;
    const unsigned sm_base = (unsigned)__cvta_generic_to_shared(sm);

    auto issue_stage = [&](int p) {
        if (p < NKSTEPS) {
            unsigned d  = sm_base + (p % STAGES) * STAGE_BYTES;
            const char* ws = wsrc0 + (size_t)p * 16 * N_DIM * 4;
            unsigned d0 = d + r0 * W_ROW_STRIDE + c16 * 16;
            asm volatile("cp.async.cg.shared.global [%0], [%1], 16;\n"
                         :: "r"(d0), "l"(ws));
            asm volatile("cp.async.cg.shared.global [%0], [%1], 16;\n"
                         :: "r"(d0 + 8 * W_ROW_STRIDE), "l"(ws + (size_t)8 * N_DIM * 4));
            if (tid < 64) {
                asm volatile("cp.async.ca.shared.global [%0], [%1], 16;\n"
                             :: "r"(d + W_STAGE_BYTES + tid * 16),
                                "l"(asrc0 + (size_t)p * A_STAGE_BYTES));
            }
        }
        asm volatile("cp.async.commit_group;\n" ::);
    };

    issue_stage(0);
    issue_stage(1);
    issue_stage(2);
    issue_stage(3);

    float acc[2][2][4] = {};

    for (int ks = 0; ks < NKSTEPS; ks++) {
        asm volatile("cp.async.wait_group 3;\n" ::);
        __syncthreads();
        issue_stage(ks + 4);   // refills the buffer consumed at iteration ks-1

        const unsigned sb = sm_base + (ks % STAGES) * STAGE_BYTES;

        // A fragments: 2 x LDS.128 (broadcast across warps)
        unsigned a[2][4];
        const unsigned ab = sb + W_STAGE_BYTES + lane * 16;
        #pragma unroll
        for (int t = 0; t < 2; t++) {
            asm volatile("ld.shared.v4.b32 {%0,%1,%2,%3}, [%4];"
                         : "=r"(a[t][0]), "=r"(a[t][1]), "=r"(a[t][2]), "=r"(a[t][3])
                         : "r"(ab + t * 512));
        }

        #pragma unroll
        for (int i = 0; i < 2; i++) {
            // B ints from smem: rows tg*2 + {0,1,8,9}, col warp*16 + i*8 + g.
            // Row stride 528B -> bank = 8*tg + g (+const) : conflict-free.
            const unsigned wb = sb + (tg * 2) * W_ROW_STRIDE + (warp * WARP_N + i * 8 + g) * 4;
            int w0, w1, w2, w3;
            asm volatile("ld.shared.b32 %0, [%1];" : "=r"(w0) : "r"(wb));
            asm volatile("ld.shared.b32 %0, [%1];" : "=r"(w1) : "r"(wb + W_ROW_STRIDE));
            asm volatile("ld.shared.b32 %0, [%1];" : "=r"(w2) : "r"(wb + 8 * W_ROW_STRIDE));
            asm volatile("ld.shared.b32 %0, [%1];" : "=r"(w3) : "r"(wb + 9 * W_ROW_STRIDE));
            __half2 p0 = __floats2half2_rn((float)w0, (float)w1);   // low = even k
            __half2 p1 = __floats2half2_rn((float)w2, (float)w3);
            unsigned b0 = *reinterpret_cast<unsigned*>(&p0);
            unsigned b1 = *reinterpret_cast<unsigned*>(&p1);

            #pragma unroll
            for (int t = 0; t < 2; t++) {
                float* c = acc[t][i];
                asm volatile(
                    "mma.sync.aligned.m16n8k16.row.col.f32.f16.f16.f32 "
                    "{%0,%1,%2,%3}, {%4,%5,%6,%7}, {%8,%9}, {%0,%1,%2,%3};"
                    : "+f"(c[0]), "+f"(c[1]), "+f"(c[2]), "+f"(c[3])
                    : "r"(a[t][0]), "r"(a[t][1]), "r"(a[t][2]), "r"(a[t][3]),
                      "r"(b0), "r"(b1));
            }
        }
    }

    // Epilogue: fp32 partials
    float* yp = g_Yp[blockIdx.y];
    #pragma unroll
    for (int t = 0; t < 2; t++) {
        #pragma unroll
        for (int i = 0; i < 2; i++) {
            const int row = t * 16 + g;
            const int col = n0cta + warp * WARP_N + i * 8 + tg * 2;
            *reinterpret_cast<float2*>(&yp[(size_t)row * N_DIM + col]) =
                make_float2(acc[t][i][0], acc[t][i][1]);
            *reinterpret_cast<float2*>(&yp[(size_t)(row + 8) * N_DIM + col]) =
                make_float2(acc[t][i][2], acc[t][i][3]);
        }
    }
}

// ---------------------------------------------------------------------------
// Kernel 3: reduce k-splits (float4).
// ---------------------------------------------------------------------------
__global__ void reduce_kernel(float* __restrict__ out) {
    int idx4 = blockIdx.x * blockDim.x + threadIdx.x;   // 0 .. 32*2048-1
    float4 s = make_float4(0.f, 0.f, 0.f, 0.f);
    #pragma unroll
    for (int sp = 0; sp < KSPLIT; sp++) {
        float4 v = reinterpret_cast<const float4*>(g_Yp[sp])[idx4];
        s.x += v.x; s.y += v.y; s.z += v.z; s.w += v.w;
    }
    reinterpret_cast<float4*>(out)[idx4] = s;
}

// ---------------------------------------------------------------------------
extern "C" void kernel_launch(void* const* d_in, const int* in_sizes, int n_in,
                              void* d_out, int out_size) {
    const float* x      = (const float*)d_in[0];   // [32, 8192] fp32
    const int*   w      = (const int*)d_in[1];     // [8192, 8192] int32 (int8-valued)
    const float* scaler = (const float*)d_in[2];   // [1] fp32
    float* out = (float*)d_out;                    // [32, 8192] fp32

    prep_pack_kernel<<<128, 256>>>(x, scaler);
    gemm_kernel<<<dim3(NSTRIPS, KSPLIT), 256>>>(w);
    reduce_kernel<<<128, 512>>>(out);
}

// round 11
// speedup vs baseline: 1.3651x; 1.0042x over previous
#include <cuda_runtime.h>
#include <cuda_fp16.h>
#include <cstdint>

// Problem dims
#define K_DIM 8192
#define N_DIM 8192

// GEMM tiling (R5/R8 empirically-best shape)
#define KSPLIT 4
#define KCHUNK (K_DIM / KSPLIT)          // 2048
#define NKSTEPS (KCHUNK / 16)            // 128 k-steps of 16
#define CTA_N 128
#define NSTRIPS (N_DIM / CTA_N)          // 64
#define WARPS 8
#define WARP_N 16                        // 2 n-tiles of 8 per warp
#define STAGES 6                         // paired k-steps: 2 consumed per barrier

// Shared-memory stage layout
#define W_ROW_BYTES (CTA_N * 4)                  // 512
#define W_ROW_STRIDE (W_ROW_BYTES + 16)          // 528 (pad -> conflict-free frag LDS)
#define W_STAGE_BYTES (16 * W_ROW_STRIDE)        // 8448
#define A_STAGE_BYTES 1024                       // 2 t-tiles * 32 lanes * 16B
#define STAGE_BYTES (W_STAGE_BYTES + A_STAGE_BYTES)  // 9472
#define SMEM_BYTES (STAGES * STAGE_BYTES)        // 56832 (dynamic)

// Scratch (allocation-free: __device__ globals)
__device__ __align__(16) __half g_Apack[32 * K_DIM];     // 512 KB, fragment-packed A
__device__ __align__(16) float g_Yp[KSPLIT][32 * N_DIM]; // 4 MB partials

// ---------------------------------------------------------------------------
// Kernel 1: fold scaler into x, fp16, fragment-pack A.
// One thread per 8B half-line (2 slots) for 2x parallelism vs R8.
// Line L (16B): ks = L>>6, t = (L>>5)&1, lane = L&31 (g = lane>>2, tg = lane&3)
// half 0 -> slots {(r0,k0),(r0+8,k0)}, half 1 -> slots at k0+8.
// ---------------------------------------------------------------------------
__global__ void prep_pack_kernel(const float* __restrict__ x,
                                 const float* __restrict__ scaler) {
    int L8 = blockIdx.x * blockDim.x + threadIdx.x;  // 0 .. 65535
    float s = scaler[0];
    int line = L8 >> 1;
    int half = L8 & 1;
    int ks   = line >> 6;
    int rem  = line & 63;
    int t    = rem >> 5;
    int lane = rem & 31;
    int g  = lane >> 2;
    int tg = lane & 3;
    int r0 = t * 16 + g;
    int k  = ks * 16 + tg * 2 + half * 8;

    float2 v0 = *reinterpret_cast<const float2*>(&x[(size_t)r0 * K_DIM + k]);
    float2 v1 = *reinterpret_cast<const float2*>(&x[(size_t)(r0 + 8) * K_DIM + k]);
    __half2 h0 = __floats2half2_rn(v0.x * s, v0.y * s);   // low = even k
    __half2 h1 = __floats2half2_rn(v1.x * s, v1.y * s);

    uint2 o;
    o.x = *reinterpret_cast<unsigned*>(&h0);
    o.y = *reinterpret_cast<unsigned*>(&h1);
    reinterpret_cast<uint2*>(g_Apack)[L8] = o;
}

// ---------------------------------------------------------------------------
// Kernel 2: cp.async-pipelined fused dequant GEMM (mma m16n8k16 f16.f32).
// CTA: 128 n-cols, 8 warps (warp_n = 16, m = 32). 6-stage pipeline,
// 2 k-steps consumed per barrier.
// ---------------------------------------------------------------------------
__global__ __launch_bounds__(256, 2) void gemm_kernel(const int* __restrict__ W) {
    extern __shared__ __align__(16) char sm[];

    const int tid  = threadIdx.x;
    const int lane = tid & 31;
    const int warp = tid >> 5;
    const int g    = lane >> 2;
    const int tg   = lane & 3;

    const int n0cta = blockIdx.x * CTA_N;
    const int krow0 = blockIdx.y * KCHUNK;     // first k row of this split
    const int ks0   = blockIdx.y * NKSTEPS;    // first global kstep (for A pack)

    // cp.async thread coords: each thread copies two 16B W granules;
    // threads [0,64) also copy one 16B A granule.
    const int r0  = tid >> 5;                  // W tile row 0..7 (and +8)
    const int c16 = tid & 31;                  // 16B column granule within row
    const char* wsrc0 = (const char*)(W + (size_t)(krow0 + r0) * N_DIM + n0cta + c16 * 4);
    const char* asrc0 = (const char*)g_Apack + (size_t)ks0 * A_STAGE_BYTES + tid * 16;
    const unsigned sm_base = (unsigned)__cvta_generic_to_shared(sm);

    auto issue_stage = [&](int p) {
        if (p < NKSTEPS) {
            unsigned d  = sm_base + (p % STAGES) * STAGE_BYTES;
            const char* ws = wsrc0 + (size_t)p * 16 * N_DIM * 4;
            unsigned d0 = d + r0 * W_ROW_STRIDE + c16 * 16;
            asm volatile("cp.async.cg.shared.global [%0], [%1], 16;\n"
                         :: "r"(d0), "l"(ws));
            asm volatile("cp.async.cg.shared.global [%0], [%1], 16;\n"
                         :: "r"(d0 + 8 * W_ROW_STRIDE), "l"(ws + (size_t)8 * N_DIM * 4));
            if (tid < 64) {
                asm volatile("cp.async.ca.shared.global [%0], [%1], 16;\n"
                             :: "r"(d + W_STAGE_BYTES + tid * 16),
                                "l"(asrc0 + (size_t)p * A_STAGE_BYTES));
            }
        }
        asm volatile("cp.async.commit_group;\n" ::);
    };

    issue_stage(0);
    issue_stage(1);
    issue_stage(2);
    issue_stage(3);

    float acc[2][2][4] = {};

    auto consume = [&](int ks) {
        const unsigned sb = sm_base + (ks % STAGES) * STAGE_BYTES;

        // A fragments: 2 x LDS.128 (broadcast across warps)
        unsigned a[2][4];
        const unsigned ab = sb + W_STAGE_BYTES + lane * 16;
        #pragma unroll
        for (int t = 0; t < 2; t++) {
            asm volatile("ld.shared.v4.b32 {%0,%1,%2,%3}, [%4];"
                         : "=r"(a[t][0]), "=r"(a[t][1]), "=r"(a[t][2]), "=r"(a[t][3])
                         : "r"(ab + t * 512));
        }

        #pragma unroll
        for (int i = 0; i < 2; i++) {
            // B ints from smem: rows tg*2 + {0,1,8,9}, col warp*16 + i*8 + g.
            // Row stride 528B -> bank = 8*tg + g (+const) : conflict-free.
            const unsigned wb = sb + (tg * 2) * W_ROW_STRIDE + (warp * WARP_N + i * 8 + g) * 4;
            int w0, w1, w2, w3;
            asm volatile("ld.shared.b32 %0, [%1];" : "=r"(w0) : "r"(wb));
            asm volatile("ld.shared.b32 %0, [%1];" : "=r"(w1) : "r"(wb + W_ROW_STRIDE));
            asm volatile("ld.shared.b32 %0, [%1];" : "=r"(w2) : "r"(wb + 8 * W_ROW_STRIDE));
            asm volatile("ld.shared.b32 %0, [%1];" : "=r"(w3) : "r"(wb + 9 * W_ROW_STRIDE));
            __half2 p0 = __floats2half2_rn((float)w0, (float)w1);   // low = even k
            __half2 p1 = __floats2half2_rn((float)w2, (float)w3);
            unsigned b0 = *reinterpret_cast<unsigned*>(&p0);
            unsigned b1 = *reinterpret_cast<unsigned*>(&p1);

            #pragma unroll
            for (int t = 0; t < 2; t++) {
                float* c = acc[t][i];
                asm volatile(
                    "mma.sync.aligned.m16n8k16.row.col.f32.f16.f16.f32 "
                    "{%0,%1,%2,%3}, {%4,%5,%6,%7}, {%8,%9}, {%0,%1,%2,%3};"
                    : "+f"(c[0]), "+f"(c[1]), "+f"(c[2]), "+f"(c[3])
                    : "r"(a[t][0]), "r"(a[t][1]), "r"(a[t][2]), "r"(a[t][3]),
                      "r"(b0), "r"(b1));
            }
        }
    };

    for (int ks = 0; ks < NKSTEPS; ks += 2) {
        // Need stages ks, ks+1 complete; 2 newer groups may stay in flight.
        asm volatile("cp.async.wait_group 2;\n" ::);
        __syncthreads();
        issue_stage(ks + 4);
        issue_stage(ks + 5);
        consume(ks);
        consume(ks + 1);
    }

    // Epilogue: fp32 partials
    float* yp = g_Yp[blockIdx.y];
    #pragma unroll
    for (int t = 0; t < 2; t++) {
        #pragma unroll
        for (int i = 0; i < 2; i++) {
            const int row = t * 16 + g;
            const int col = n0cta + warp * WARP_N + i * 8 + tg * 2;
            *reinterpret_cast<float2*>(&yp[(size_t)row * N_DIM + col]) =
                make_float2(acc[t][i][0], acc[t][i][1]);
            *reinterpret_cast<float2*>(&yp[(size_t)(row + 8) * N_DIM + col]) =
                make_float2(acc[t][i][2], acc[t][i][3]);
        }
    }
}

// ---------------------------------------------------------------------------
// Kernel 3: reduce k-splits (float4).
// ---------------------------------------------------------------------------
__global__ void reduce_kernel(float* __restrict__ out) {
    int idx4 = blockIdx.x * blockDim.x + threadIdx.x;   // 0 .. 32*2048-1
    float4 s = make_float4(0.f, 0.f, 0.f, 0.f);
    #pragma unroll
    for (int sp = 0; sp < KSPLIT; sp++) {
        float4 v = reinterpret_cast<const float4*>(g_Yp[sp])[idx4];
        s.x += v.x; s.y += v.y; s.z += v.z; s.w += v.w;
    }
    reinterpret_cast<float4*>(out)[idx4] = s;
}

// ---------------------------------------------------------------------------
extern "C" void kernel_launch(void* const* d_in, const int* in_sizes, int n_in,
                              void* d_out, int out_size) {
    const float* x      = (const float*)d_in[0];   // [32, 8192] fp32
    const int*   w      = (const int*)d_in[1];     // [8192, 8192] int32 (int8-valued)
    const float* scaler = (const float*)d_in[2];   // [1] fp32
    float* out = (float*)d_out;                    // [32, 8192] fp32

    static bool attr_set = false;
    if (!attr_set) {
        cudaFuncSetAttribute(gemm_kernel,
                             cudaFuncAttributeMaxDynamicSharedMemorySize, SMEM_BYTES);
        attr_set = true;
    }

    prep_pack_kernel<<<256, 256>>>(x, scaler);
    gemm_kernel<<<dim3(NSTRIPS, KSPLIT), 256, SMEM_BYTES>>>(w);
    reduce_kernel<<<128, 512>>>(out);
}